// round 12
// baseline (speedup 1.0000x reference)
#include <cuda_runtime.h>
#include <cuda_fp16.h>
#include <cstdint>

// ---------------- problem constants ----------------
#define KTOT   3072
#define NOUT   12288
#define MB     64             // batch (GEMM N side)
#define MTILE  32             // output rows per CTA
#define KC     64             // K per chunk
#define NCHUNK (KTOT / KC)    // 48
#define NTH    256
#define NCTA   (NOUT / MTILE) // 384

// ---- smem layout ----
// B stages   : 3 x (64 rows x 128B fp16, SW128)  at 0
// scales     : 3 x 256B                          at 24576
// A packed   : 2 x (32 rows x 64B int8)          at 25344
// bias       : 128B                              at 33792 (above epi region)
#define SM_B(s)   ((uint32_t)(s) * 8192u)
#define SM_S(s)   (24576u + (uint32_t)(s) * 256u)
#define SM_APK(b) (25344u + (uint32_t)(b) * 2048u)
#define SM_BIAS   33792u
#define SMEM_TOTAL 33920u
#define EPI_RSTRIDE 33        // floats per row in epilogue warp region

// x pre-converted to fp16, k-permuted within every 16-half window so that
// lane q's mma fragment slots correspond to data k = 4q..4q+3.
__device__ __align__(16) __half g_xh[MB * KTOT];

__global__ void xconv_kernel(const float* __restrict__ x) {
    int wdx = blockIdx.x * blockDim.x + threadIdx.x;   // window index (16 halves)
    const float* src = x + (size_t)wdx * 16;
    __half h[16];
#pragma unroll
    for (int p = 0; p < 16; p++) {
        // hw position p holds data d(p): d(2q+r)=4q+r, d(8+2q+r)=4q+2+r
        int q = (p >> 1) & 3, rr = p & 1, hh = p >> 3;
        h[p] = __float2half(src[4 * q + 2 * hh + rr]);
    }
    uint4* dst = (uint4*)(g_xh + (size_t)wdx * 16);
    dst[0] = *(uint4*)&h[0];
    dst[1] = *(uint4*)&h[8];
}

// ---------------- device helpers ----------------
__device__ __forceinline__ uint32_t smem_u32(const void* p) {
    uint32_t a;
    asm("{ .reg .u64 t; cvta.to.shared.u64 t, %1; cvt.u32.u64 %0, t; }" : "=r"(a) : "l"(p));
    return a;
}
__device__ __forceinline__ uint32_t swz(uint32_t off) {  // SW128 Swizzle<3,4,3>
    return off ^ ((off >> 3) & 0x70u);
}
__device__ __forceinline__ void cp_async16(uint32_t dst, const void* src) {
    asm volatile("cp.async.cg.shared.global [%0], [%1], 16;"
                 :: "r"(dst), "l"(src) : "memory");
}
__device__ __forceinline__ void cp_async8(uint32_t dst, const void* src) {
    asm volatile("cp.async.ca.shared.global [%0], [%1], 8;"
                 :: "r"(dst), "l"(src) : "memory");
}
#define CP_COMMIT()  asm volatile("cp.async.commit_group;" ::: "memory")
#define CP_WAIT(n)   asm volatile("cp.async.wait_group %0;" :: "n"(n) : "memory")

__device__ __forceinline__ void sts32(uint32_t addr, uint32_t v) {
    asm volatile("st.shared.b32 [%0], %1;" :: "r"(addr), "r"(v) : "memory");
}
__device__ __forceinline__ uint32_t lds32(uint32_t addr) {
    uint32_t v;
    asm volatile("ld.shared.b32 %0, [%1];" : "=r"(v) : "r"(addr));
    return v;
}
__device__ __forceinline__ void ldsm4(uint32_t* r, uint32_t addr) {
    asm volatile("ldmatrix.sync.aligned.m8n8.x4.shared.b16 {%0,%1,%2,%3}, [%4];"
                 : "=r"(r[0]), "=r"(r[1]), "=r"(r[2]), "=r"(r[3]) : "r"(addr));
}
__device__ __forceinline__ void mma16816(float* c,
                                         uint32_t a0, uint32_t a1, uint32_t a2, uint32_t a3,
                                         uint32_t b0, uint32_t b1) {
    asm volatile(
        "mma.sync.aligned.m16n8k16.row.col.f32.f16.f16.f32 "
        "{%0,%1,%2,%3}, {%4,%5,%6,%7}, {%8,%9}, {%0,%1,%2,%3};"
        : "+f"(c[0]), "+f"(c[1]), "+f"(c[2]), "+f"(c[3])
        : "r"(a0), "r"(a1), "r"(a2), "r"(a3), "r"(b0), "r"(b1));
}
// pack low bytes of 4 int32 codes into one word
__device__ __forceinline__ uint32_t pack4(int4 c) {
    uint32_t u = __byte_perm((uint32_t)c.x, (uint32_t)c.y, 0x0040);
    uint32_t v = __byte_perm((uint32_t)c.z, (uint32_t)c.w, 0x0040);
    return __byte_perm(u, v, 0x5410);
}

__global__ __launch_bounds__(NTH, 3)
void dql_kernel(const int*   __restrict__ wq,
                const float* __restrict__ ws,
                const int*   __restrict__ bq,
                const float* __restrict__ bs,
                float*       __restrict__ out) {
    extern __shared__ __align__(16) char smem[];
    const uint32_t sb = smem_u32(smem);
    float* smf = (float*)smem;

    const int tid  = threadIdx.x;
    const int lane = tid & 31;
    const int wid  = tid >> 5;
    const int wk   = wid >> 1;     // k-split quarter (16 data-k per warp per chunk)
    const int wn   = wid & 1;      // batch half (32)
    const int cta  = blockIdx.x;

    // bias for this CTA's 32 output rows
    if (tid < MTILE) {
        const int o = cta * MTILE + tid;
        ((float*)(smem + SM_BIAS))[tid] = ((float)bq[o] - 128.0f) * bs[o >> 5];
    }

    // ---- A producer mapping: LDG raw codes, pack to int8, STS ----
    const int a_R = tid >> 3;      // 0..31 (weight row)
    const int a_s = tid & 7;       // 4-code segment (covers segs a_s, a_s+8)
    const int* a_src = wq + (size_t)(cta * MTILE + a_R) * KTOT + a_s * 4;
    const uint32_t a_pv = (uint32_t)(((a_R >> 1) & 3) << 2);   // XOR word swizzle
    const uint32_t a_w0 = ((uint32_t)a_s        ^ a_pv) * 4;
    const uint32_t a_w1 = ((uint32_t)(a_s + 8)  ^ a_pv) * 4;
    const uint32_t a_rowb = (uint32_t)(a_R * 64);

    // ---- B cp.async mapping ----
    const int brow = tid >> 2;     // 0..63 (batch row)
    const int bseg = tid & 3;
    const char* b_src0 = (const char*)(g_xh + (size_t)brow * KTOT) + bseg * 16;
    const char* s_src0 = (const char*)(ws + (size_t)(cta * MTILE + tid) * (KTOT / 32));

    auto issueB = [&](int c) {
        const uint32_t st = sb + SM_B(c % 3);
        const char* s = b_src0 + (size_t)c * (KC * 2);
        cp_async16(st + swz((uint32_t)(brow * 128 + bseg * 16)), s);
        cp_async16(st + swz((uint32_t)(brow * 128 + (bseg + 4) * 16)), s + 64);
        if (tid < MTILE)
            cp_async8(sb + SM_S(c % 3) + (uint32_t)(tid * 8), s_src0 + (size_t)c * 8);
    };

    int4 ar0, ar1;                 // LDG staging (one chunk)
    auto ldgA = [&](int c) {
        const int* p = a_src + c * KC;
        ar0 = *(const int4*)(p);
        ar1 = *(const int4*)(p + 32);
    };
    auto stsA = [&](int c) {       // pack + store into APK[c&1]
        const uint32_t base = sb + SM_APK(c & 1) + a_rowb;
        sts32(base + a_w0, pack4(ar0));
        sts32(base + a_w1, pack4(ar1));
    };

    float acc[2][4][4];
#pragma unroll
    for (int mf = 0; mf < 2; mf++)
#pragma unroll
        for (int nf = 0; nf < 4; nf++)
#pragma unroll
            for (int i = 0; i < 4; i++) acc[mf][nf][i] = 0.0f;

    // ---- consumer addressing ----
    const int r  = lane >> 2;                      // fragment base row
    const int q  = lane & 3;                       // fragment k sub-lane
    const int kb4 = (wk >> 1) * 4;                 // scale word sel within float2
    const uint32_t wbase = (uint32_t)(wk * 4 + q); // word index within 16
    const uint32_t b_lrow = (uint32_t)(wn * 32 + (lane & 7) + ((lane >> 4) & 1) * 8);
    const uint32_t b_lcol = (uint32_t)(((lane >> 3) & 1) * 16);
    const uint32_t kcol   = (uint32_t)(wk * 32);   // B byte window
    const __half2 c1152 = __half2(__ushort_as_half((unsigned short)0x6480),
                                  __ushort_as_half((unsigned short)0x6480));

    // ---- prologue ----
    issueB(0); CP_COMMIT();
    issueB(1); CP_COMMIT();
    ldgA(0); stsA(0);
    ldgA(1);

    for (int c = 0; c < NCHUNK; c++) {
        CP_WAIT(1);                  // B stage c complete
        __syncthreads();             // + APK[c&1] (stored last iter) visible

        if (c + 2 < NCHUNK) issueB(c + 2);
        CP_COMMIT();
        if (c + 1 < NCHUNK) {
            stsA(c + 1);             // from staging regs (loaded last iter)
            if (c + 2 < NCHUNK) ldgA(c + 2);
        }

        // ---- consume chunk c ----
        const uint32_t APK = sb + SM_APK(c & 1);
        const uint32_t Ss  = sb + SM_S(c % 3);
        const uint32_t Bs  = sb + SM_B(c % 3);

        uint32_t a[2][4];
#pragma unroll
        for (int j = 0; j < 4; j++) {
            const int R = r + 8 * j;
            float s = __uint_as_float(lds32(Ss + (uint32_t)(R * 8 + kb4)));
            const __half2 s2 = __float2half2_rn(s);
            const uint32_t pv = (uint32_t)(((R >> 1) & 3) << 2);
            uint32_t packed = lds32(APK + (uint32_t)(R * 64) + ((wbase ^ pv) * 4));
            uint32_t h01 = __byte_perm(packed, 0x64006400u, 0x5150);
            uint32_t h23 = __byte_perm(packed, 0x64006400u, 0x5352);
            __half2 v0 = __hmul2(__hsub2(*(__half2*)&h01, c1152), s2);
            __half2 v1 = __hmul2(__hsub2(*(__half2*)&h23, c1152), s2);
            a[j >> 1][(j & 1)]     = *(uint32_t*)&v0;   // k-group 0
            a[j >> 1][2 + (j & 1)] = *(uint32_t*)&v1;   // k-group 1
        }

        uint32_t b[2][4];
#pragma unroll
        for (int nf2 = 0; nf2 < 2; nf2++)
            ldsm4(b[nf2], Bs + swz((b_lrow + (uint32_t)(nf2 * 16)) * 128 + kcol + b_lcol));

#pragma unroll
        for (int mf = 0; mf < 2; mf++)
#pragma unroll
            for (int nf = 0; nf < 4; nf++) {
                const int u = nf >> 1;
                const int p = (nf & 1) * 2;
                mma16816(acc[mf][nf], a[mf][0], a[mf][1], a[mf][2], a[mf][3],
                         b[u][p], b[u][p + 1]);
            }
    }

    // ---- epilogue: per-warp partials -> smem, reduce over wk, bias, store ----
    __syncthreads();
    {
        const uint32_t wb = (uint32_t)(wid * 32 * EPI_RSTRIDE);
        const int g = lane >> 2;
        const int qq = (lane & 3) * 2;
#pragma unroll
        for (int mf = 0; mf < 2; mf++)
#pragma unroll
            for (int nf = 0; nf < 4; nf++) {
                const int row = mf * 16 + g;
                const int col = nf * 8 + qq;
                smf[wb + row * EPI_RSTRIDE + col]            = acc[mf][nf][0];
                smf[wb + row * EPI_RSTRIDE + col + 1]        = acc[mf][nf][1];
                smf[wb + (row + 8) * EPI_RSTRIDE + col]      = acc[mf][nf][2];
                smf[wb + (row + 8) * EPI_RSTRIDE + col + 1]  = acc[mf][nf][3];
            }
    }
    __syncthreads();
    {
        const int row = tid & 31;
        const int mg  = tid >> 5;
        const float bias = ((const float*)(smem + SM_BIAS))[row];
        float* op = out + (size_t)cta * MTILE + row;
#pragma unroll
        for (int j = 0; j < 8; j++) {
            const int m   = mg * 8 + j;
            const int wn_ = m >> 5;
            const int ml  = m & 31;
            float v = bias;
#pragma unroll
            for (int k4 = 0; k4 < 4; k4++)
                v += smf[(uint32_t)((k4 * 2 + wn_) * 32 * EPI_RSTRIDE + row * EPI_RSTRIDE + ml)];
            op[(size_t)m * NOUT] = v;
        }
    }
}

extern "C" void kernel_launch(void* const* d_in, const int* in_sizes, int n_in,
                              void* d_out, int out_size) {
    (void)in_sizes; (void)n_in; (void)out_size;
    xconv_kernel<<<(MB * KTOT / 16) / NTH, NTH>>>((const float*)d_in[0]);
    cudaFuncSetAttribute(dql_kernel, cudaFuncAttributeMaxDynamicSharedMemorySize, SMEM_TOTAL);
    dql_kernel<<<NCTA, NTH, SMEM_TOTAL>>>(
        (const int*)d_in[1],     // w_q
        (const float*)d_in[2],   // w_scales
        (const int*)d_in[3],     // b_q
        (const float*)d_in[4],   // b_scales
        (float*)d_out);
}